// round 1
// baseline (speedup 1.0000x reference)
#include <cuda_runtime.h>
#include <cuda_bf16.h>
#include <math.h>

// ---------------- problem constants ----------------
#define BATCH   32
#define CHN     384
#define HH      28
#define WW      28
#define NTOK    784            // 28*28
#define HEADS   12
#define HDIM    32
#define HIDDEN  1536
#define MROWS   (BATCH*NTOK)   // 25088
#define SCALE_K 0.17677669529663687f  // 32^-0.5

// ---------------- scratch (static device arrays; no allocation) ----------------
__device__ float g_nchwA[BATCH*CHN*NTOK];
__device__ float g_nchwB[BATCH*CHN*NTOK];
__device__ float g_xt[MROWS*CHN];
__device__ float g_cur[MROWS*CHN];
__device__ float g_qkv[(size_t)MROWS*3*CHN];
__device__ float g_attn[BATCH*HEADS*HDIM*HDIM];
__device__ float g_attnout[MROWS*CHN];
__device__ float g_x2[MROWS*CHN];
__device__ float g_x3[MROWS*CHN];
__device__ float g_hidden[(size_t)MROWS*HIDDEN];
__device__ float g_y[MROWS*CHN];

// ---------------- depthwise 3x3 conv + residual (NCHW -> NCHW) ----------------
__global__ void dwconv_res(const float* __restrict__ x, const float* __restrict__ w,
                           const float* __restrict__ bias, float* __restrict__ y)
{
    int bc = blockIdx.x;            // b*CHN + c
    int c  = bc % CHN;
    const float* xp = x + (size_t)bc * NTOK;
    float*       yp = y + (size_t)bc * NTOK;

    __shared__ float s[NTOK];
    __shared__ float wk[9];
    for (int i = threadIdx.x; i < NTOK; i += blockDim.x) s[i] = xp[i];
    if (threadIdx.x < 9) wk[threadIdx.x] = w[c*9 + threadIdx.x];
    __syncthreads();

    float bb = bias[c];
    for (int i = threadIdx.x; i < NTOK; i += blockDim.x) {
        int h = i / WW, q = i % WW;
        float acc = bb;
        #pragma unroll
        for (int dh = -1; dh <= 1; dh++) {
            #pragma unroll
            for (int dw = -1; dw <= 1; dw++) {
                int hh = h + dh, ww2 = q + dw;
                if (hh >= 0 && hh < HH && ww2 >= 0 && ww2 < WW)
                    acc += wk[(dh+1)*3 + (dw+1)] * s[hh*WW + ww2];
            }
        }
        yp[i] = s[i] + acc;
    }
}

// ---------------- per-batch matrix transpose: in (B,R,S) -> out (B,S,R) ----------------
__global__ void btranspose(const float* __restrict__ in, float* __restrict__ out, int R, int S)
{
    __shared__ float tile[32][33];
    int b  = blockIdx.z;
    int r0 = blockIdx.y * 32, s0 = blockIdx.x * 32;
    const float* ip = in  + (size_t)b * R * S;
    float*       op = out + (size_t)b * R * S;

    int tx = threadIdx.x, ty = threadIdx.y;
    #pragma unroll
    for (int i = 0; i < 32; i += 8) {
        int rr = r0 + ty + i, ss = s0 + tx;
        if (rr < R && ss < S) tile[ty+i][tx] = ip[(size_t)rr * S + ss];
    }
    __syncthreads();
    #pragma unroll
    for (int i = 0; i < 32; i += 8) {
        int ss = s0 + ty + i, rr = r0 + tx;
        if (ss < S && rr < R) op[(size_t)ss * R + rr] = tile[tx][ty+i];
    }
}

// ---------------- layernorm over last dim (C=384), rows = B*N ----------------
__device__ __forceinline__ float warp_sum(float s) {
    #pragma unroll
    for (int o = 16; o > 0; o >>= 1) s += __shfl_xor_sync(0xffffffffu, s, o);
    return s;
}

__global__ void layernorm_k(const float* __restrict__ in, const float* __restrict__ g,
                            const float* __restrict__ bt, float* __restrict__ out)
{
    int row = blockIdx.x;
    int tid = threadIdx.x;          // 128 threads
    int lane = tid & 31, wid = tid >> 5;
    const float* ip = in + (size_t)row * CHN;

    float v0 = ip[tid], v1 = ip[tid+128], v2 = ip[tid+256];
    __shared__ float sred[8];

    float s = warp_sum(v0 + v1 + v2);
    if (lane == 0) sred[wid] = s;
    __syncthreads();
    float mean = (sred[0]+sred[1]+sred[2]+sred[3]) * (1.0f/CHN);

    float d0 = v0-mean, d1 = v1-mean, d2 = v2-mean;
    float s2 = warp_sum(d0*d0 + d1*d1 + d2*d2);
    if (lane == 0) sred[4+wid] = s2;
    __syncthreads();
    float var = (sred[4]+sred[5]+sred[6]+sred[7]) * (1.0f/CHN);
    float rstd = rsqrtf(var + 1e-5f);

    float* op = out + (size_t)row * CHN;
    op[tid]     = d0*rstd*g[tid]     + bt[tid];
    op[tid+128] = d1*rstd*g[tid+128] + bt[tid+128];
    op[tid+256] = d2*rstd*g[tid+256] + bt[tid+256];
}

// ---------------- generic SGEMM: C(M,N) = A(M,K) * W(N,K)^T  (+bias, gelu, +res) ----------------
// Requires M%64==0, N%64==0, K%16==0 (all shapes here satisfy this).
__global__ void __launch_bounds__(256, 2) sgemm_nt(
    const float* __restrict__ A, const float* __restrict__ W,
    const float* __restrict__ bias, const float* __restrict__ res,
    float* __restrict__ Cout, int Md, int Nd, int Kd, int act)
{
    __shared__ float As[16][65];
    __shared__ float Bs[16][65];

    int tid = threadIdx.x;
    int tn = tid & 15, tm = tid >> 4;        // 16x16 thread grid
    int m0 = blockIdx.y * 64, n0 = blockIdx.x * 64;

    const float* Ap = A + (size_t)m0 * Kd;
    const float* Wp = W + (size_t)n0 * Kd;

    int lr = tid >> 2;          // 0..63
    int lc = (tid & 3) * 4;     // 0,4,8,12

    float acc[4][4];
    #pragma unroll
    for (int i = 0; i < 4; i++)
        #pragma unroll
        for (int j = 0; j < 4; j++) acc[i][j] = 0.0f;

    for (int k0 = 0; k0 < Kd; k0 += 16) {
        float4 a4 = *(const float4*)(Ap + (size_t)lr * Kd + k0 + lc);
        float4 b4 = *(const float4*)(Wp + (size_t)lr * Kd + k0 + lc);
        As[lc+0][lr] = a4.x; As[lc+1][lr] = a4.y; As[lc+2][lr] = a4.z; As[lc+3][lr] = a4.w;
        Bs[lc+0][lr] = b4.x; Bs[lc+1][lr] = b4.y; Bs[lc+2][lr] = b4.z; Bs[lc+3][lr] = b4.w;
        __syncthreads();

        #pragma unroll
        for (int k = 0; k < 16; k++) {
            float ar[4], br[4];
            #pragma unroll
            for (int i = 0; i < 4; i++) ar[i] = As[k][tm + 16*i];
            #pragma unroll
            for (int j = 0; j < 4; j++) br[j] = Bs[k][tn + 16*j];
            #pragma unroll
            for (int i = 0; i < 4; i++)
                #pragma unroll
                for (int j = 0; j < 4; j++) acc[i][j] = fmaf(ar[i], br[j], acc[i][j]);
        }
        __syncthreads();
    }

    #pragma unroll
    for (int i = 0; i < 4; i++) {
        int m = m0 + tm + 16*i;
        #pragma unroll
        for (int j = 0; j < 4; j++) {
            int n = n0 + tn + 16*j;
            float v = acc[i][j];
            if (bias) v += bias[n];
            if (act)  v = 0.5f * v * (1.0f + erff(v * 0.70710678118654752f)); // exact GELU
            if (res)  v += res[(size_t)m * Nd + n];
            Cout[(size_t)m * Nd + n] = v;
        }
    }
}

// ---------------- channel attention: logits[b,h,d,e] = SCALE * sum_n k[n,d]*v[n,e] ----------------
__global__ void attn_kv_k(const float* __restrict__ qkv, float* __restrict__ attn)
{
    int bh = blockIdx.x;
    int b = bh / HEADS, h = bh % HEADS;
    const float* kb = qkv + (size_t)b * NTOK * (3*CHN) + CHN   + h*HDIM;
    const float* vb = qkv + (size_t)b * NTOK * (3*CHN) + 2*CHN + h*HDIM;

    __shared__ float ks[32][33], vs[32][33];
    int e  = threadIdx.x & 31;
    int dg = threadIdx.x >> 5;     // 0..7
    float acc[4] = {0.f, 0.f, 0.f, 0.f};

    for (int n0 = 0; n0 < NTOK; n0 += 32) {
        #pragma unroll
        for (int r = 0; r < 4; r++) {
            int nl = (threadIdx.x >> 5) + r*8;
            int dl = threadIdx.x & 31;
            int n = n0 + nl;
            ks[nl][dl] = (n < NTOK) ? kb[(size_t)n * (3*CHN) + dl] : 0.f;
            vs[nl][dl] = (n < NTOK) ? vb[(size_t)n * (3*CHN) + dl] : 0.f;
        }
        __syncthreads();
        #pragma unroll 8
        for (int nl = 0; nl < 32; nl++) {
            float vv = vs[nl][e];
            #pragma unroll
            for (int i = 0; i < 4; i++) acc[i] = fmaf(ks[nl][dg + 8*i], vv, acc[i]);
        }
        __syncthreads();
    }
    #pragma unroll
    for (int i = 0; i < 4; i++) {
        int d = dg + 8*i;
        attn[(size_t)bh * (HDIM*HDIM) + d*HDIM + e] = acc[i] * SCALE_K;
    }
}

// ---------------- softmax over e (rows of length 32) ----------------
__global__ void softmax32(float* __restrict__ attn)
{
    int r = blockIdx.x * 4 + (threadIdx.x >> 5);
    int lane = threadIdx.x & 31;
    float* p = attn + (size_t)r * 32;
    float v = p[lane];
    float m = v;
    #pragma unroll
    for (int o = 16; o > 0; o >>= 1) m = fmaxf(m, __shfl_xor_sync(0xffffffffu, m, o));
    float ex = expf(v - m);
    float s = ex;
    #pragma unroll
    for (int o = 16; o > 0; o >>= 1) s += __shfl_xor_sync(0xffffffffu, s, o);
    p[lane] = ex / s;
}

// ---------------- out[b,n,h,d] = sum_e attn[b,h,d,e] * q[b,n,h,e] ----------------
__global__ void attn_apply_k(const float* __restrict__ qkv, const float* __restrict__ attn,
                             float* __restrict__ out)
{
    int bh = blockIdx.x;
    int b = bh / HEADS, h = bh % HEADS;
    int n0 = blockIdx.y * 64;

    __shared__ float As[32][33];
    __shared__ float qs[8][33];

    #pragma unroll
    for (int r = 0; r < 4; r++) {
        int idx = threadIdx.x + r*256;
        As[idx >> 5][idx & 31] = attn[(size_t)bh * (HDIM*HDIM) + idx];
    }
    const float* qb = qkv + (size_t)b * NTOK * (3*CHN) + h*HDIM;
    int d  = threadIdx.x & 31;
    int nl = threadIdx.x >> 5;     // 0..7
    __syncthreads();

    for (int r = 0; r < 8; r++) {
        int n = n0 + r*8 + nl;
        qs[nl][d] = (n < NTOK) ? qb[(size_t)n * (3*CHN) + d] : 0.f;
        __syncthreads();
        float acc = 0.f;
        #pragma unroll
        for (int e = 0; e < 32; e++) acc = fmaf(qs[nl][e], As[d][e], acc);
        if (n < NTOK)
            out[((size_t)b * NTOK + n) * CHN + h*HDIM + d] = acc;
        __syncthreads();
    }
}

// ---------------- host launcher ----------------
extern "C" void kernel_launch(void* const* d_in, const int* in_sizes, int n_in,
                              void* d_out, int out_size)
{
    const float* x      = (const float*)d_in[0];
    const float* cpe1_w = (const float*)d_in[1];
    const float* cpe1_b = (const float*)d_in[2];
    const float* n1_g   = (const float*)d_in[3];
    const float* n1_b   = (const float*)d_in[4];
    const float* qkv_w  = (const float*)d_in[5];
    const float* proj_w = (const float*)d_in[6];
    const float* proj_b = (const float*)d_in[7];
    const float* cpe2_w = (const float*)d_in[8];
    const float* cpe2_b = (const float*)d_in[9];
    const float* n2_g   = (const float*)d_in[10];
    const float* n2_b   = (const float*)d_in[11];
    const float* fc1_w  = (const float*)d_in[12];
    const float* fc1_b  = (const float*)d_in[13];
    const float* fc2_w  = (const float*)d_in[14];
    const float* fc2_b  = (const float*)d_in[15];
    float* out = (float*)d_out;

    float *p_nchwA, *p_nchwB, *p_xt, *p_cur, *p_qkv, *p_attn, *p_attnout, *p_x2, *p_x3, *p_hidden, *p_y;
    cudaGetSymbolAddress((void**)&p_nchwA,   g_nchwA);
    cudaGetSymbolAddress((void**)&p_nchwB,   g_nchwB);
    cudaGetSymbolAddress((void**)&p_xt,      g_xt);
    cudaGetSymbolAddress((void**)&p_cur,     g_cur);
    cudaGetSymbolAddress((void**)&p_qkv,     g_qkv);
    cudaGetSymbolAddress((void**)&p_attn,    g_attn);
    cudaGetSymbolAddress((void**)&p_attnout, g_attnout);
    cudaGetSymbolAddress((void**)&p_x2,      g_x2);
    cudaGetSymbolAddress((void**)&p_x3,      g_x3);
    cudaGetSymbolAddress((void**)&p_hidden,  g_hidden);
    cudaGetSymbolAddress((void**)&p_y,       g_y);

    dim3 t328(32, 8);

    // 1) x = x + dwconv1(x)                    (NCHW)
    dwconv_res<<<BATCH*CHN, 256>>>(x, cpe1_w, cpe1_b, p_nchwA);
    // 2) transpose -> token-major xt (B,N,C)
    btranspose<<<dim3(25, 12, BATCH), t328>>>(p_nchwA, p_xt, CHN, NTOK);
    // 3) cur = LN(xt)
    layernorm_k<<<MROWS, 128>>>(p_xt, n1_g, n1_b, p_cur);
    // 4) qkv = cur @ qkv_w^T
    sgemm_nt<<<dim3(18, 392), 256>>>(p_cur, qkv_w, nullptr, nullptr, p_qkv, MROWS, 3*CHN, CHN, 0);
    // 5) channel-attention logits K^T V (scaled)
    attn_kv_k<<<BATCH*HEADS, 256>>>(p_qkv, p_attn);
    // 6) softmax over e
    softmax32<<<(BATCH*HEADS*HDIM)/4, 128>>>(p_attn);
    // 7) out = attn @ q
    attn_apply_k<<<dim3(BATCH*HEADS, 13), 256>>>(p_qkv, p_attn, p_attnout);
    // 8) x2 = xt + attnout @ proj_w^T + proj_b
    sgemm_nt<<<dim3(6, 392), 256>>>(p_attnout, proj_w, proj_b, p_xt, p_x2, MROWS, CHN, CHN, 0);
    // 9) to NCHW
    btranspose<<<dim3(12, 25, BATCH), t328>>>(p_x2, p_nchwA, NTOK, CHN);
    // 10) x = x + dwconv2(x)
    dwconv_res<<<BATCH*CHN, 256>>>(p_nchwA, cpe2_w, cpe2_b, p_nchwB);
    // 11) back to token-major x3
    btranspose<<<dim3(25, 12, BATCH), t328>>>(p_nchwB, p_x3, CHN, NTOK);
    // 12) cur = LN(x3)
    layernorm_k<<<MROWS, 128>>>(p_x3, n2_g, n2_b, p_cur);
    // 13) hidden = gelu(cur @ fc1^T + b1)
    sgemm_nt<<<dim3(24, 392), 256>>>(p_cur, fc1_w, fc1_b, nullptr, p_hidden, MROWS, HIDDEN, CHN, 1);
    // 14) y = x3 + hidden @ fc2^T + b2
    sgemm_nt<<<dim3(6, 392), 256>>>(p_hidden, fc2_w, fc2_b, p_x3, p_y, MROWS, CHN, HIDDEN, 0);
    // 15) final transpose to (B,C,H,W)
    btranspose<<<dim3(12, 25, BATCH), t328>>>(p_y, out, NTOK, CHN);
}

// round 4
// speedup vs baseline: 3.3430x; 3.3430x over previous
#include <cuda_runtime.h>
#include <cuda_bf16.h>
#include <math.h>
#include <stdint.h>

// ---------------- problem constants ----------------
#define BATCH   32
#define CHN     384
#define HH      28
#define WW      28
#define NTOK    784
#define HEADS   12
#define HDIM    32
#define HIDDEN  1536
#define MROWS   (BATCH*NTOK)       // 25088
#define KP1     (3*CHN)            // 1152
#define KP2     (3*HIDDEN)         // 4608
#define SCALE_K 0.17677669529663687f

// ---------------- scratch ----------------
__device__ float g_nchwA[BATCH*CHN*NTOK];
__device__ float g_nchwB[BATCH*CHN*NTOK];
__device__ float g_xt[MROWS*CHN];
__device__ float g_qkv[(size_t)MROWS*3*CHN];
__device__ float g_attn[BATCH*HEADS*HDIM*HDIM];
__device__ float g_x2[MROWS*CHN];
__device__ float g_x3[MROWS*CHN];
__device__ float g_y[MROWS*CHN];
// split-bf16 activations [rows, 3K]  layout [hi|hi|lo]
__device__ __nv_bfloat16 g_curS[(size_t)MROWS*KP1];
__device__ __nv_bfloat16 g_aoS[(size_t)MROWS*KP1];
__device__ __nv_bfloat16 g_hidS[(size_t)MROWS*KP2];
// split-bf16 weights [N, 3K]  layout [hi|lo|hi]
__device__ __nv_bfloat16 g_wqkvS[(size_t)(3*CHN)*KP1];
__device__ __nv_bfloat16 g_wprojS[(size_t)CHN*KP1];
__device__ __nv_bfloat16 g_wfc1S[(size_t)HIDDEN*KP1];
__device__ __nv_bfloat16 g_wfc2S[(size_t)CHN*KP2];

// ---------------- helpers ----------------
__device__ __forceinline__ uint32_t smem_u32(const void* p) {
    uint32_t a;
    asm("{ .reg .u64 t; cvta.to.shared.u64 t, %1; cvt.u32.u64 %0, t; }" : "=r"(a) : "l"(p));
    return a;
}
#define CP16(dst, src) \
    asm volatile("cp.async.cg.shared.global [%0], [%1], 16;" :: "r"(dst), "l"(src))
#define CP_COMMIT() asm volatile("cp.async.commit_group;" ::: "memory")
#define CP_WAIT2()  asm volatile("cp.async.wait_group 2;" ::: "memory")

#define LDMX4(r0,r1,r2,r3,addr) \
    asm volatile("ldmatrix.sync.aligned.m8n8.x4.shared.b16 {%0,%1,%2,%3}, [%4];" \
                 : "=r"(r0), "=r"(r1), "=r"(r2), "=r"(r3) : "r"(addr))

#define MMA16816(d, a, b) \
    asm volatile("mma.sync.aligned.m16n8k16.row.col.f32.bf16.bf16.f32 " \
        "{%0,%1,%2,%3}, {%4,%5,%6,%7}, {%8,%9}, {%0,%1,%2,%3};" \
        : "+f"((d)[0]), "+f"((d)[1]), "+f"((d)[2]), "+f"((d)[3]) \
        : "r"((a)[0]), "r"((a)[1]), "r"((a)[2]), "r"((a)[3]), "r"((b)[0]), "r"((b)[1]))

// ---------------- mma.sync bf16 GEMM ----------------
// C(M,N) = A'(M,K') * W'(N,K')^T.  BM=BN=128, BK=32, 4-stage cp.async.
// Stage layout: A tile 128x32 bf16 (8KB) + B tile 128x32 (8KB); row=64B,
// 16B-chunk swizzle: c' = c ^ ((row>>1)&3).
#define STG_SZ   16384
#define GEMM_SMEM (4*STG_SZ)

__device__ __forceinline__ void issue_chunk(
    uint32_t sb, int st, const char* Ab, const char* Bb,
    int m0, int n0, int Kp, int kk, int tid)
{
    uint32_t sA = sb + st * STG_SZ;
    uint32_t sB = sA + 8192;
    #pragma unroll
    for (int i = 0; i < 2; i++) {
        int id = tid + (i << 8);
        int r = id >> 2, c = id & 3;
        const char* g = Ab + (((size_t)(m0 + r) * Kp + kk + (c << 3)) << 1);
        uint32_t d = sA + (r << 6) + ((c ^ ((r >> 1) & 3)) << 4);
        CP16(d, g);
    }
    #pragma unroll
    for (int i = 0; i < 2; i++) {
        int id = tid + (i << 8);
        int r = id >> 2, c = id & 3;
        const char* g = Bb + (((size_t)(n0 + r) * Kp + kk + (c << 3)) << 1);
        uint32_t d = sB + (r << 6) + ((c ^ ((r >> 1) & 3)) << 4);
        CP16(d, g);
    }
}

__global__ void __launch_bounds__(256, 2) gemm_mma(
    const __nv_bfloat16* __restrict__ A, const __nv_bfloat16* __restrict__ Bw,
    const float* __restrict__ bias, const float* __restrict__ res,
    float* __restrict__ outF, __nv_bfloat16* __restrict__ outS,
    int Ntot, int Kp, int act)
{
    extern __shared__ __align__(128) char smem[];
    uint32_t sb = smem_u32(smem);
    int tid = threadIdx.x, lane = tid & 31, w = tid >> 5;
    int wm0 = (w & 1) * 64;          // 2 m-warps
    int wn0 = (w >> 1) * 32;         // 4 n-warps
    int m0 = blockIdx.y * 128, n0 = blockIdx.x * 128;

    const char* Ab = (const char*)A;
    const char* Bb = (const char*)Bw;
    int nch = Kp >> 5;

    float acc[4][4][4];
    #pragma unroll
    for (int i = 0; i < 4; i++)
        #pragma unroll
        for (int j = 0; j < 4; j++)
            #pragma unroll
            for (int q = 0; q < 4; q++) acc[i][j][q] = 0.f;

    // prologue: 3 stages in flight
    issue_chunk(sb, 0, Ab, Bb, m0, n0, Kp, 0,  tid); CP_COMMIT();
    issue_chunk(sb, 1, Ab, Bb, m0, n0, Kp, 32, tid); CP_COMMIT();
    issue_chunk(sb, 2, Ab, Bb, m0, n0, Kp, 64, tid); CP_COMMIT();

    for (int ch = 0; ch < nch; ch++) {
        CP_WAIT2();
        __syncthreads();
        if (ch + 3 < nch)
            issue_chunk(sb, (ch + 3) & 3, Ab, Bb, m0, n0, Kp, (ch + 3) << 5, tid);
        CP_COMMIT();

        uint32_t sA = sb + (ch & 3) * STG_SZ;
        uint32_t sB = sA + 8192;

        #pragma unroll
        for (int ks = 0; ks < 2; ks++) {
            int k0 = ks << 4;
            uint32_t a[4][4], b[4][2];
            #pragma unroll
            for (int mt = 0; mt < 4; mt++) {
                uint32_t r = wm0 + mt * 16 + (lane & 15);
                uint32_t kc = (k0 >> 3) + (lane >> 4);
                uint32_t addr = sA + (r << 6) + ((kc ^ ((r >> 1) & 3)) << 4);
                LDMX4(a[mt][0], a[mt][1], a[mt][2], a[mt][3], addr);
            }
            #pragma unroll
            for (int ntp = 0; ntp < 2; ntp++) {
                uint32_t j = lane >> 3;
                uint32_t nt = ntp * 2 + (j >> 1);
                uint32_t kc = (k0 >> 3) + (j & 1);
                uint32_t r = wn0 + nt * 8 + (lane & 7);
                uint32_t addr = sB + (r << 6) + ((kc ^ ((r >> 1) & 3)) << 4);
                uint32_t q0, q1, q2, q3;
                LDMX4(q0, q1, q2, q3, addr);
                b[ntp*2][0] = q0;   b[ntp*2][1] = q1;
                b[ntp*2+1][0] = q2; b[ntp*2+1][1] = q3;
            }
            #pragma unroll
            for (int mt = 0; mt < 4; mt++)
                #pragma unroll
                for (int nt = 0; nt < 4; nt++)
                    MMA16816(acc[mt][nt], a[mt], b[nt]);
        }
        __syncthreads();
    }

    // epilogue straight from register fragments
    int mrow = wm0 + (lane >> 2);
    int ncol = wn0 + (lane & 3) * 2;
    #pragma unroll
    for (int mt = 0; mt < 4; mt++) {
        #pragma unroll
        for (int nt = 0; nt < 4; nt++) {
            int m = m0 + mrow + mt * 16;
            int n = n0 + ncol + nt * 8;
            float v0 = acc[mt][nt][0], v1 = acc[mt][nt][1];
            float v2 = acc[mt][nt][2], v3 = acc[mt][nt][3];
            if (bias) {
                float2 bb = *(const float2*)(bias + n);
                v0 += bb.x; v1 += bb.y; v2 += bb.x; v3 += bb.y;
            }
            if (act) {
                v0 = 0.5f*v0*(1.0f+erff(v0*0.70710678118654752f));
                v1 = 0.5f*v1*(1.0f+erff(v1*0.70710678118654752f));
                v2 = 0.5f*v2*(1.0f+erff(v2*0.70710678118654752f));
                v3 = 0.5f*v3*(1.0f+erff(v3*0.70710678118654752f));
                // split-bf16 store [hi|hi|lo] over row stride 3*Ntot
                #pragma unroll
                for (int h = 0; h < 2; h++) {
                    float a0 = h ? v2 : v0, a1 = h ? v3 : v1;
                    size_t mm = (size_t)(m + h*8);
                    __nv_bfloat16 h0 = __float2bfloat16(a0);
                    __nv_bfloat16 h1 = __float2bfloat16(a1);
                    __nv_bfloat16 l0 = __float2bfloat16(a0 - __bfloat162float(h0));
                    __nv_bfloat16 l1 = __float2bfloat16(a1 - __bfloat162float(h1));
                    __nv_bfloat162 hp; hp.x = h0; hp.y = h1;
                    __nv_bfloat162 lp; lp.x = l0; lp.y = l1;
                    size_t base = mm * (size_t)(3*Ntot) + n;
                    *(__nv_bfloat162*)(outS + base) = hp;
                    *(__nv_bfloat162*)(outS + base + Ntot) = hp;
                    *(__nv_bfloat162*)(outS + base + 2*(size_t)Ntot) = lp;
                }
            } else {
                if (res) {
                    float2 r0 = *(const float2*)(res + (size_t)m * Ntot + n);
                    float2 r1 = *(const float2*)(res + (size_t)(m+8) * Ntot + n);
                    v0 += r0.x; v1 += r0.y; v2 += r1.x; v3 += r1.y;
                }
                float2 o0; o0.x = v0; o0.y = v1;
                float2 o1; o1.x = v2; o1.y = v3;
                *(float2*)(outF + (size_t)m * Ntot + n) = o0;
                *(float2*)(outF + (size_t)(m+8) * Ntot + n) = o1;
            }
        }
    }
}

// ---------------- weight split: [N,K] fp32 -> [N,3K] bf16 [hi|lo|hi] ----------------
__global__ void weight_split(const float* __restrict__ w, __nv_bfloat16* __restrict__ o,
                             int Nn, int Kk)
{
    int idx = blockIdx.x * 256 + threadIdx.x;
    if (idx >= Nn * Kk) return;
    int r = idx / Kk, c = idx % Kk;
    float v = w[idx];
    __nv_bfloat16 hi = __float2bfloat16(v);
    __nv_bfloat16 lo = __float2bfloat16(v - __bfloat162float(hi));
    size_t base = (size_t)r * (3 * Kk) + c;
    o[base] = hi;
    o[base + Kk] = lo;
    o[base + 2 * (size_t)Kk] = hi;
}

// ---------------- depthwise 3x3 conv + residual ----------------
__global__ void dwconv_res(const float* __restrict__ x, const float* __restrict__ w,
                           const float* __restrict__ bias, float* __restrict__ y)
{
    int bc = blockIdx.x;
    int c  = bc % CHN;
    const float* xp = x + (size_t)bc * NTOK;
    float*       yp = y + (size_t)bc * NTOK;

    __shared__ float s[NTOK];
    __shared__ float wk[9];
    for (int i = threadIdx.x; i < NTOK; i += blockDim.x) s[i] = xp[i];
    if (threadIdx.x < 9) wk[threadIdx.x] = w[c*9 + threadIdx.x];
    __syncthreads();

    float bb = bias[c];
    for (int i = threadIdx.x; i < NTOK; i += blockDim.x) {
        int h = i / WW, q = i % WW;
        float acc = bb;
        #pragma unroll
        for (int dh = -1; dh <= 1; dh++)
            #pragma unroll
            for (int dw = -1; dw <= 1; dw++) {
                int hh = h + dh, ww2 = q + dw;
                if (hh >= 0 && hh < HH && ww2 >= 0 && ww2 < WW)
                    acc += wk[(dh+1)*3 + (dw+1)] * s[hh*WW + ww2];
            }
        yp[i] = s[i] + acc;
    }
}

// ---------------- per-batch transpose (B,R,S) -> (B,S,R) ----------------
__global__ void btranspose(const float* __restrict__ in, float* __restrict__ out, int R, int S)
{
    __shared__ float tile[32][33];
    int b  = blockIdx.z;
    int r0 = blockIdx.y * 32, s0 = blockIdx.x * 32;
    const float* ip = in  + (size_t)b * R * S;
    float*       op = out + (size_t)b * R * S;

    int tx = threadIdx.x, ty = threadIdx.y;
    #pragma unroll
    for (int i = 0; i < 32; i += 8) {
        int rr = r0 + ty + i, ss = s0 + tx;
        if (rr < R && ss < S) tile[ty+i][tx] = ip[(size_t)rr * S + ss];
    }
    __syncthreads();
    #pragma unroll
    for (int i = 0; i < 32; i += 8) {
        int ss = s0 + ty + i, rr = r0 + tx;
        if (ss < S && rr < R) op[(size_t)ss * R + rr] = tile[tx][ty+i];
    }
}

// ---------------- layernorm -> split-bf16 [hi|hi|lo] ----------------
__device__ __forceinline__ float warp_sum(float s) {
    #pragma unroll
    for (int o = 16; o > 0; o >>= 1) s += __shfl_xor_sync(0xffffffffu, s, o);
    return s;
}

__global__ void layernorm_split(const float* __restrict__ in, const float* __restrict__ g,
                                const float* __restrict__ bt, __nv_bfloat16* __restrict__ out)
{
    int row = blockIdx.x;
    int tid = threadIdx.x;          // 128
    int lane = tid & 31, wid = tid >> 5;
    const float* ip = in + (size_t)row * CHN;

    float v0 = ip[tid], v1 = ip[tid+128], v2 = ip[tid+256];
    __shared__ float sred[8];

    float s = warp_sum(v0 + v1 + v2);
    if (lane == 0) sred[wid] = s;
    __syncthreads();
    float mean = (sred[0]+sred[1]+sred[2]+sred[3]) * (1.0f/CHN);

    float d0 = v0-mean, d1 = v1-mean, d2 = v2-mean;
    float s2 = warp_sum(d0*d0 + d1*d1 + d2*d2);
    if (lane == 0) sred[4+wid] = s2;
    __syncthreads();
    float var = (sred[4]+sred[5]+sred[6]+sred[7]) * (1.0f/CHN);
    float rstd = rsqrtf(var + 1e-5f);

    __nv_bfloat16* op = out + (size_t)row * (3*CHN);
    #pragma unroll
    for (int j = 0; j < 3; j++) {
        int cidx = tid + j*128;
        float d = (j==0) ? d0 : (j==1) ? d1 : d2;
        float val = d*rstd*g[cidx] + bt[cidx];
        __nv_bfloat16 hi = __float2bfloat16(val);
        __nv_bfloat16 lo = __float2bfloat16(val - __bfloat162float(hi));
        op[cidx] = hi;
        op[CHN + cidx] = hi;
        op[2*CHN + cidx] = lo;
    }
}

// ---------------- channel attention ----------------
__global__ void attn_kv_k(const float* __restrict__ qkv, float* __restrict__ attn)
{
    int bh = blockIdx.x;
    int b = bh / HEADS, h = bh % HEADS;
    const float* kb = qkv + (size_t)b * NTOK * (3*CHN) + CHN   + h*HDIM;
    const float* vb = qkv + (size_t)b * NTOK * (3*CHN) + 2*CHN + h*HDIM;

    __shared__ float ks[32][33], vs[32][33];
    int e  = threadIdx.x & 31;
    int dg = threadIdx.x >> 5;
    float acc[4] = {0.f, 0.f, 0.f, 0.f};

    for (int n0 = 0; n0 < NTOK; n0 += 32) {
        #pragma unroll
        for (int r = 0; r < 4; r++) {
            int nl = (threadIdx.x >> 5) + r*8;
            int dl = threadIdx.x & 31;
            int n = n0 + nl;
            ks[nl][dl] = (n < NTOK) ? kb[(size_t)n * (3*CHN) + dl] : 0.f;
            vs[nl][dl] = (n < NTOK) ? vb[(size_t)n * (3*CHN) + dl] : 0.f;
        }
        __syncthreads();
        #pragma unroll 8
        for (int nl = 0; nl < 32; nl++) {
            float vv = vs[nl][e];
            #pragma unroll
            for (int i = 0; i < 4; i++) acc[i] = fmaf(ks[nl][dg + 8*i], vv, acc[i]);
        }
        __syncthreads();
    }
    #pragma unroll
    for (int i = 0; i < 4; i++) {
        int d = dg + 8*i;
        attn[(size_t)bh * (HDIM*HDIM) + d*HDIM + e] = acc[i] * SCALE_K;
    }
}

__global__ void softmax32(float* __restrict__ attn)
{
    int r = blockIdx.x * 4 + (threadIdx.x >> 5);
    int lane = threadIdx.x & 31;
    float* p = attn + (size_t)r * 32;
    float v = p[lane];
    float m = v;
    #pragma unroll
    for (int o = 16; o > 0; o >>= 1) m = fmaxf(m, __shfl_xor_sync(0xffffffffu, m, o));
    float ex = expf(v - m);
    float s = ex;
    #pragma unroll
    for (int o = 16; o > 0; o >>= 1) s += __shfl_xor_sync(0xffffffffu, s, o);
    p[lane] = ex / s;
}

__global__ void attn_apply_split(const float* __restrict__ qkv, const float* __restrict__ attn,
                                 __nv_bfloat16* __restrict__ out)
{
    int bh = blockIdx.x;
    int b = bh / HEADS, h = bh % HEADS;
    int n0 = blockIdx.y * 64;

    __shared__ float As[32][33];
    __shared__ float qs[8][33];

    #pragma unroll
    for (int r = 0; r < 4; r++) {
        int idx = threadIdx.x + r*256;
        As[idx >> 5][idx & 31] = attn[(size_t)bh * (HDIM*HDIM) + idx];
    }
    const float* qb = qkv + (size_t)b * NTOK * (3*CHN) + h*HDIM;
    int d  = threadIdx.x & 31;
    int nl = threadIdx.x >> 5;
    __syncthreads();

    for (int r = 0; r < 8; r++) {
        int n = n0 + r*8 + nl;
        qs[nl][d] = (n < NTOK) ? qb[(size_t)n * (3*CHN) + d] : 0.f;
        __syncthreads();
        float acc = 0.f;
        #pragma unroll
        for (int e = 0; e < 32; e++) acc = fmaf(qs[nl][e], As[d][e], acc);
        if (n < NTOK) {
            __nv_bfloat16 hi = __float2bfloat16(acc);
            __nv_bfloat16 lo = __float2bfloat16(acc - __bfloat162float(hi));
            size_t base = ((size_t)b * NTOK + n) * (3*CHN) + h*HDIM + d;
            out[base] = hi;
            out[base + CHN] = hi;
            out[base + 2*CHN] = lo;
        }
        __syncthreads();
    }
}

// ---------------- host launcher ----------------
extern "C" void kernel_launch(void* const* d_in, const int* in_sizes, int n_in,
                              void* d_out, int out_size)
{
    const float* x      = (const float*)d_in[0];
    const float* cpe1_w = (const float*)d_in[1];
    const float* cpe1_b = (const float*)d_in[2];
    const float* n1_g   = (const float*)d_in[3];
    const float* n1_b   = (const float*)d_in[4];
    const float* qkv_w  = (const float*)d_in[5];
    const float* proj_w = (const float*)d_in[6];
    const float* proj_b = (const float*)d_in[7];
    const float* cpe2_w = (const float*)d_in[8];
    const float* cpe2_b = (const float*)d_in[9];
    const float* n2_g   = (const float*)d_in[10];
    const float* n2_b   = (const float*)d_in[11];
    const float* fc1_w  = (const float*)d_in[12];
    const float* fc1_b  = (const float*)d_in[13];
    const float* fc2_w  = (const float*)d_in[14];
    const float* fc2_b  = (const float*)d_in[15];
    float* out = (float*)d_out;

    float *p_nchwA, *p_nchwB, *p_xt, *p_qkv, *p_attn, *p_x2, *p_x3, *p_y;
    __nv_bfloat16 *p_curS, *p_aoS, *p_hidS, *p_wqkvS, *p_wprojS, *p_wfc1S, *p_wfc2S;
    cudaGetSymbolAddress((void**)&p_nchwA,  g_nchwA);
    cudaGetSymbolAddress((void**)&p_nchwB,  g_nchwB);
    cudaGetSymbolAddress((void**)&p_xt,     g_xt);
    cudaGetSymbolAddress((void**)&p_qkv,    g_qkv);
    cudaGetSymbolAddress((void**)&p_attn,   g_attn);
    cudaGetSymbolAddress((void**)&p_x2,     g_x2);
    cudaGetSymbolAddress((void**)&p_x3,     g_x3);
    cudaGetSymbolAddress((void**)&p_y,      g_y);
    cudaGetSymbolAddress((void**)&p_curS,   g_curS);
    cudaGetSymbolAddress((void**)&p_aoS,    g_aoS);
    cudaGetSymbolAddress((void**)&p_hidS,   g_hidS);
    cudaGetSymbolAddress((void**)&p_wqkvS,  g_wqkvS);
    cudaGetSymbolAddress((void**)&p_wprojS, g_wprojS);
    cudaGetSymbolAddress((void**)&p_wfc1S,  g_wfc1S);
    cudaGetSymbolAddress((void**)&p_wfc2S,  g_wfc2S);

    cudaFuncSetAttribute(gemm_mma, cudaFuncAttributeMaxDynamicSharedMemorySize, GEMM_SMEM);

    dim3 t328(32, 8);

    // weight splits (cheap)
    weight_split<<<(3*CHN*CHN + 255)/256, 256>>>(qkv_w,  p_wqkvS,  3*CHN, CHN);
    weight_split<<<(CHN*CHN + 255)/256,   256>>>(proj_w, p_wprojS, CHN,   CHN);
    weight_split<<<(HIDDEN*CHN + 255)/256,256>>>(fc1_w,  p_wfc1S,  HIDDEN, CHN);
    weight_split<<<(CHN*HIDDEN + 255)/256,256>>>(fc2_w,  p_wfc2S,  CHN,   HIDDEN);

    // 1) x = x + dwconv1(x)
    dwconv_res<<<BATCH*CHN, 256>>>(x, cpe1_w, cpe1_b, p_nchwA);
    // 2) transpose -> token-major xt (B,N,C)
    btranspose<<<dim3(25, 12, BATCH), t328>>>(p_nchwA, p_xt, CHN, NTOK);
    // 3) curS = split(LN(xt))
    layernorm_split<<<MROWS, 128>>>(p_xt, n1_g, n1_b, p_curS);
    // 4) qkv = cur @ qkv_w^T   (mma.sync bf16, split-K' exact)
    gemm_mma<<<dim3((3*CHN)/128, MROWS/128), 256, GEMM_SMEM>>>(
        p_curS, p_wqkvS, nullptr, nullptr, p_qkv, nullptr, 3*CHN, KP1, 0);
    // 5-7) channel attention
    attn_kv_k<<<BATCH*HEADS, 256>>>(p_qkv, p_attn);
    softmax32<<<(BATCH*HEADS*HDIM)/4, 128>>>(p_attn);
    attn_apply_split<<<dim3(BATCH*HEADS, 13), 256>>>(p_qkv, p_attn, p_aoS);
    // 8) x2 = xt + ao @ proj_w^T + proj_b
    gemm_mma<<<dim3(CHN/128, MROWS/128), 256, GEMM_SMEM>>>(
        p_aoS, p_wprojS, proj_b, p_xt, p_x2, nullptr, CHN, KP1, 0);
    // 9) to NCHW
    btranspose<<<dim3(12, 25, BATCH), t328>>>(p_x2, p_nchwA, NTOK, CHN);
    // 10) x = x + dwconv2(x)
    dwconv_res<<<BATCH*CHN, 256>>>(p_nchwA, cpe2_w, cpe2_b, p_nchwB);
    // 11) back to token-major x3
    btranspose<<<dim3(25, 12, BATCH), t328>>>(p_nchwB, p_x3, CHN, NTOK);
    // 12) curS = split(LN(x3))
    layernorm_split<<<MROWS, 128>>>(p_x3, n2_g, n2_b, p_curS);
    // 13) hidS = split(gelu(cur @ fc1^T + b1))
    gemm_mma<<<dim3(HIDDEN/128, MROWS/128), 256, GEMM_SMEM>>>(
        p_curS, p_wfc1S, fc1_b, nullptr, nullptr, p_hidS, HIDDEN, KP1, 1);
    // 14) y = x3 + hid @ fc2^T + b2
    gemm_mma<<<dim3(CHN/128, MROWS/128), 256, GEMM_SMEM>>>(
        p_hidS, p_wfc2S, fc2_b, p_x3, p_y, nullptr, CHN, KP2, 0);
    // 15) final transpose to (B,C,H,W)
    btranspose<<<dim3(12, 25, BATCH), t328>>>(p_y, out, NTOK, CHN);
}

// round 5
// speedup vs baseline: 3.4659x; 1.0368x over previous
#include <cuda_runtime.h>
#include <cuda_bf16.h>
#include <math.h>
#include <stdint.h>

// ---------------- problem constants ----------------
#define BATCH   32
#define CHN     384
#define HH      28
#define WW      28
#define NTOK    784
#define HEADS   12
#define HDIM    32
#define HIDDEN  1536
#define MROWS   (BATCH*NTOK)       // 25088
#define SCALE_K 0.17677669529663687f

// ---------------- scratch ----------------
__device__ float g_nchwA[BATCH*CHN*NTOK];
__device__ float g_xt[MROWS*CHN];
__device__ float g_qkv[(size_t)MROWS*3*CHN];
__device__ float g_attn[BATCH*HEADS*HDIM*HDIM];
__device__ float g_x2[MROWS*CHN];
__device__ float g_x3[MROWS*CHN];
__device__ float g_y[MROWS*CHN];
// dedup split activations [rows, 2K]  layout [hi|lo]
__device__ __align__(16) __nv_bfloat16 g_curS[(size_t)MROWS*2*CHN];
__device__ __align__(16) __nv_bfloat16 g_aoS[(size_t)MROWS*2*CHN];
__device__ __align__(16) __nv_bfloat16 g_hidS[(size_t)MROWS*2*HIDDEN];
// dedup split weights [N, 2K]  layout [hi|lo]
__device__ __align__(16) __nv_bfloat16 g_wqkvS[(size_t)(3*CHN)*2*CHN];
__device__ __align__(16) __nv_bfloat16 g_wprojS[(size_t)CHN*2*CHN];
__device__ __align__(16) __nv_bfloat16 g_wfc1S[(size_t)HIDDEN*2*CHN];
__device__ __align__(16) __nv_bfloat16 g_wfc2S[(size_t)CHN*2*HIDDEN];

// ---------------- helpers ----------------
__device__ __forceinline__ uint32_t smem_u32(const void* p) {
    uint32_t a;
    asm("{ .reg .u64 t; cvta.to.shared.u64 t, %1; cvt.u32.u64 %0, t; }" : "=r"(a) : "l"(p));
    return a;
}
#define CP16(dst, src) \
    asm volatile("cp.async.cg.shared.global [%0], [%1], 16;" :: "r"(dst), "l"(src))
#define CP_COMMIT() asm volatile("cp.async.commit_group;" ::: "memory")
#define CP_WAIT2()  asm volatile("cp.async.wait_group 2;" ::: "memory")

#define LDMX4(r0,r1,r2,r3,addr) \
    asm volatile("ldmatrix.sync.aligned.m8n8.x4.shared.b16 {%0,%1,%2,%3}, [%4];" \
                 : "=r"(r0), "=r"(r1), "=r"(r2), "=r"(r3) : "r"(addr))

#define MMA16816(d, a, b) \
    asm volatile("mma.sync.aligned.m16n8k16.row.col.f32.bf16.bf16.f32 " \
        "{%0,%1,%2,%3}, {%4,%5,%6,%7}, {%8,%9}, {%0,%1,%2,%3};" \
        : "+f"((d)[0]), "+f"((d)[1]), "+f"((d)[2]), "+f"((d)[3]) \
        : "r"((a)[0]), "r"((a)[1]), "r"((a)[2]), "r"((a)[3]), "r"((b)[0]), "r"((b)[1]))

// ---------------- mma.sync bf16 GEMM with 3-phase split-K' mapping ----------------
// C = A*B^T computed as Ah*Bh + Ah*Bl + Al*Bh from dedup [hi|lo] buffers.
// BM=BN=128, BK=32, 4-stage cp.async, swizzle c' = c ^ ((row>>1)&3).
#define STG_SZ   16384
#define GEMM_SMEM (4*STG_SZ)

// chunk ch in [0, 3*nk1): phase 0 -> Ah*Bh, 1 -> Ah*Bl, 2 -> Al*Bh
__device__ __forceinline__ void chunk_off(int ch, int nk1, int Kb, int& aoff, int& boff) {
    int phase = (ch >= 2*nk1) ? 2 : ((ch >= nk1) ? 1 : 0);
    int off = (ch - phase * nk1) << 5;
    aoff = off + ((phase == 2) ? Kb : 0);
    boff = off + ((phase == 1) ? Kb : 0);
}

__device__ __forceinline__ void issue_chunk(
    uint32_t sb, int st, const char* Ab, const char* Bb,
    int m0, int n0, int twoKb, int aoff, int boff, int tid)
{
    uint32_t sA = sb + st * STG_SZ;
    uint32_t sB = sA + 8192;
    #pragma unroll
    for (int i = 0; i < 2; i++) {
        int id = tid + (i << 8);
        int r = id >> 2, c = id & 3;
        const char* g = Ab + (((size_t)(m0 + r) * twoKb + aoff + (c << 3)) << 1);
        uint32_t d = sA + (r << 6) + ((c ^ ((r >> 1) & 3)) << 4);
        CP16(d, g);
    }
    #pragma unroll
    for (int i = 0; i < 2; i++) {
        int id = tid + (i << 8);
        int r = id >> 2, c = id & 3;
        const char* g = Bb + (((size_t)(n0 + r) * twoKb + boff + (c << 3)) << 1);
        uint32_t d = sB + (r << 6) + ((c ^ ((r >> 1) & 3)) << 4);
        CP16(d, g);
    }
}

__global__ void __launch_bounds__(256, 2) gemm_mma(
    const __nv_bfloat16* __restrict__ A, const __nv_bfloat16* __restrict__ Bw,
    const float* __restrict__ bias, const float* __restrict__ res,
    float* __restrict__ outF, __nv_bfloat16* __restrict__ outS,
    int Ntot, int Kb, int act)
{
    extern __shared__ __align__(128) char smem[];
    uint32_t sb = smem_u32(smem);
    int tid = threadIdx.x, lane = tid & 31, w = tid >> 5;
    int wm0 = (w & 1) * 64;
    int wn0 = (w >> 1) * 32;
    int m0 = blockIdx.y * 128, n0 = blockIdx.x * 128;

    const char* Ab = (const char*)A;
    const char* Bb = (const char*)Bw;
    int nk1 = Kb >> 5;
    int nch = 3 * nk1;
    int twoKb = 2 * Kb;

    float acc[4][4][4];
    #pragma unroll
    for (int i = 0; i < 4; i++)
        #pragma unroll
        for (int j = 0; j < 4; j++)
            #pragma unroll
            for (int q = 0; q < 4; q++) acc[i][j][q] = 0.f;

    {
        int ao, bo;
        chunk_off(0, nk1, Kb, ao, bo);
        issue_chunk(sb, 0, Ab, Bb, m0, n0, twoKb, ao, bo, tid); CP_COMMIT();
        chunk_off(1, nk1, Kb, ao, bo);
        issue_chunk(sb, 1, Ab, Bb, m0, n0, twoKb, ao, bo, tid); CP_COMMIT();
        chunk_off(2, nk1, Kb, ao, bo);
        issue_chunk(sb, 2, Ab, Bb, m0, n0, twoKb, ao, bo, tid); CP_COMMIT();
    }

    for (int ch = 0; ch < nch; ch++) {
        CP_WAIT2();
        __syncthreads();
        if (ch + 3 < nch) {
            int ao, bo;
            chunk_off(ch + 3, nk1, Kb, ao, bo);
            issue_chunk(sb, (ch + 3) & 3, Ab, Bb, m0, n0, twoKb, ao, bo, tid);
        }
        CP_COMMIT();

        uint32_t sA = sb + (ch & 3) * STG_SZ;
        uint32_t sB = sA + 8192;

        #pragma unroll
        for (int ks = 0; ks < 2; ks++) {
            int k0 = ks << 4;
            uint32_t a[4][4], b[4][2];
            #pragma unroll
            for (int mt = 0; mt < 4; mt++) {
                uint32_t r = wm0 + mt * 16 + (lane & 15);
                uint32_t kc = (k0 >> 3) + (lane >> 4);
                uint32_t addr = sA + (r << 6) + ((kc ^ ((r >> 1) & 3)) << 4);
                LDMX4(a[mt][0], a[mt][1], a[mt][2], a[mt][3], addr);
            }
            #pragma unroll
            for (int ntp = 0; ntp < 2; ntp++) {
                uint32_t j = lane >> 3;
                uint32_t nt = ntp * 2 + (j >> 1);
                uint32_t kc = (k0 >> 3) + (j & 1);
                uint32_t r = wn0 + nt * 8 + (lane & 7);
                uint32_t addr = sB + (r << 6) + ((kc ^ ((r >> 1) & 3)) << 4);
                uint32_t q0, q1, q2, q3;
                LDMX4(q0, q1, q2, q3, addr);
                b[ntp*2][0] = q0;   b[ntp*2][1] = q1;
                b[ntp*2+1][0] = q2; b[ntp*2+1][1] = q3;
            }
            #pragma unroll
            for (int mt = 0; mt < 4; mt++)
                #pragma unroll
                for (int nt = 0; nt < 4; nt++)
                    MMA16816(acc[mt][nt], a[mt], b[nt]);
        }
    }

    // epilogue from register fragments
    int mrow = wm0 + (lane >> 2);
    int ncol = wn0 + (lane & 3) * 2;
    #pragma unroll
    for (int mt = 0; mt < 4; mt++) {
        #pragma unroll
        for (int nt = 0; nt < 4; nt++) {
            int m = m0 + mrow + mt * 16;
            int n = n0 + ncol + nt * 8;
            float v0 = acc[mt][nt][0], v1 = acc[mt][nt][1];
            float v2 = acc[mt][nt][2], v3 = acc[mt][nt][3];
            if (bias) {
                float2 bb = *(const float2*)(bias + n);
                v0 += bb.x; v1 += bb.y; v2 += bb.x; v3 += bb.y;
            }
            if (act) {
                v0 = 0.5f*v0*(1.0f+erff(v0*0.70710678118654752f));
                v1 = 0.5f*v1*(1.0f+erff(v1*0.70710678118654752f));
                v2 = 0.5f*v2*(1.0f+erff(v2*0.70710678118654752f));
                v3 = 0.5f*v3*(1.0f+erff(v3*0.70710678118654752f));
                #pragma unroll
                for (int h = 0; h < 2; h++) {
                    float a0 = h ? v2 : v0, a1 = h ? v3 : v1;
                    size_t mm = (size_t)(m + h*8);
                    __nv_bfloat16 h0 = __float2bfloat16(a0);
                    __nv_bfloat16 h1 = __float2bfloat16(a1);
                    __nv_bfloat16 l0 = __float2bfloat16(a0 - __bfloat162float(h0));
                    __nv_bfloat16 l1 = __float2bfloat16(a1 - __bfloat162float(h1));
                    __nv_bfloat162 hp; hp.x = h0; hp.y = h1;
                    __nv_bfloat162 lp; lp.x = l0; lp.y = l1;
                    size_t base = mm * (size_t)(2*Ntot) + n;
                    *(__nv_bfloat162*)(outS + base) = hp;
                    *(__nv_bfloat162*)(outS + base + Ntot) = lp;
                }
            } else {
                if (res) {
                    float2 r0 = *(const float2*)(res + (size_t)m * Ntot + n);
                    float2 r1 = *(const float2*)(res + (size_t)(m+8) * Ntot + n);
                    v0 += r0.x; v1 += r0.y; v2 += r1.x; v3 += r1.y;
                }
                float2 o0; o0.x = v0; o0.y = v1;
                float2 o1; o1.x = v2; o1.y = v3;
                *(float2*)(outF + (size_t)m * Ntot + n) = o0;
                *(float2*)(outF + (size_t)(m+8) * Ntot + n) = o1;
            }
        }
    }
}

// ---------------- all weight splits in one launch: [N,K] fp32 -> [N,2K] [hi|lo] ----------------
__global__ void weight_split_all(
    const float* __restrict__ w0, __nv_bfloat16* __restrict__ o0,
    const float* __restrict__ w1, __nv_bfloat16* __restrict__ o1,
    const float* __restrict__ w2, __nv_bfloat16* __restrict__ o2,
    const float* __restrict__ w3, __nv_bfloat16* __restrict__ o3)
{
    int seg = blockIdx.y;
    const float* w; __nv_bfloat16* o; int cnt, Kk;
    if (seg == 0)      { w = w0; o = o0; cnt = 3*CHN*CHN;  Kk = CHN; }
    else if (seg == 1) { w = w1; o = o1; cnt = CHN*CHN;    Kk = CHN; }
    else if (seg == 2) { w = w2; o = o2; cnt = HIDDEN*CHN; Kk = CHN; }
    else               { w = w3; o = o3; cnt = CHN*HIDDEN; Kk = HIDDEN; }
    int idx = blockIdx.x * 256 + threadIdx.x;
    if (idx >= cnt) return;
    int r = idx / Kk, c = idx % Kk;
    float v = w[idx];
    __nv_bfloat16 hi = __float2bfloat16(v);
    __nv_bfloat16 lo = __float2bfloat16(v - __bfloat162float(hi));
    size_t base = (size_t)r * (2 * Kk) + c;
    o[base] = hi;
    o[base + Kk] = lo;
}

// ---------------- depthwise 3x3 conv + residual (NCHW) ----------------
__global__ void dwconv_res(const float* __restrict__ x, const float* __restrict__ w,
                           const float* __restrict__ bias, float* __restrict__ y)
{
    int bc = blockIdx.x;
    int c  = bc % CHN;
    const float* xp = x + (size_t)bc * NTOK;
    float*       yp = y + (size_t)bc * NTOK;

    __shared__ float s[NTOK];
    __shared__ float wk[9];
    for (int i = threadIdx.x; i < NTOK; i += blockDim.x) s[i] = xp[i];
    if (threadIdx.x < 9) wk[threadIdx.x] = w[c*9 + threadIdx.x];
    __syncthreads();

    float bb = bias[c];
    for (int i = threadIdx.x; i < NTOK; i += blockDim.x) {
        int h = i / WW, q = i % WW;
        float acc = bb;
        #pragma unroll
        for (int dh = -1; dh <= 1; dh++)
            #pragma unroll
            for (int dw = -1; dw <= 1; dw++) {
                int hh = h + dh, ww2 = q + dw;
                if (hh >= 0 && hh < HH && ww2 >= 0 && ww2 < WW)
                    acc += wk[(dh+1)*3 + (dw+1)] * s[hh*WW + ww2];
            }
        yp[i] = s[i] + acc;
    }
}

// ---------------- token-major depthwise 3x3 + residual: (B,N,C) -> (B,N,C) ----------------
__global__ void dwconv_tok(const float* __restrict__ t, const float* __restrict__ w,
                           const float* __restrict__ bias, float* __restrict__ y)
{
    __shared__ float sw[CHN*9];
    int b = blockIdx.y, h = blockIdx.x;
    int c = threadIdx.x;                 // 384 threads
    for (int i = c; i < CHN*9; i += CHN) sw[i] = w[i];
    __syncthreads();

    float wr[9];
    #pragma unroll
    for (int j = 0; j < 9; j++) wr[j] = sw[c*9 + j];
    float bb = bias[c];

    const float* tb = t + (size_t)b * NTOK * CHN;
    float* yb = y + (size_t)b * NTOK * CHN;

    for (int q = 0; q < WW; q++) {
        float acc = bb;
        float center = 0.f;
        #pragma unroll
        for (int dh = -1; dh <= 1; dh++) {
            int hh = h + dh;
            if ((unsigned)hh >= HH) continue;
            #pragma unroll
            for (int dw = -1; dw <= 1; dw++) {
                int ww2 = q + dw;
                if ((unsigned)ww2 >= WW) continue;
                float val = __ldg(tb + (size_t)(hh*WW + ww2) * CHN + c);
                acc += wr[(dh+1)*3 + (dw+1)] * val;
                if (dh == 0 && dw == 0) center = val;
            }
        }
        yb[(size_t)(h*WW + q) * CHN + c] = center + acc;
    }
}

// ---------------- layernorm -> dedup split [hi|lo] ----------------
__device__ __forceinline__ float warp_sum(float s) {
    #pragma unroll
    for (int o = 16; o > 0; o >>= 1) s += __shfl_xor_sync(0xffffffffu, s, o);
    return s;
}

__global__ void layernorm_split(const float* __restrict__ in, const float* __restrict__ g,
                                const float* __restrict__ bt, __nv_bfloat16* __restrict__ out)
{
    int row = blockIdx.x;
    int tid = threadIdx.x;          // 128
    int lane = tid & 31, wid = tid >> 5;
    const float* ip = in + (size_t)row * CHN;

    float v0 = ip[tid], v1 = ip[tid+128], v2 = ip[tid+256];
    __shared__ float sred[8];

    float s = warp_sum(v0 + v1 + v2);
    if (lane == 0) sred[wid] = s;
    __syncthreads();
    float mean = (sred[0]+sred[1]+sred[2]+sred[3]) * (1.0f/CHN);

    float d0 = v0-mean, d1 = v1-mean, d2 = v2-mean;
    float s2 = warp_sum(d0*d0 + d1*d1 + d2*d2);
    if (lane == 0) sred[4+wid] = s2;
    __syncthreads();
    float var = (sred[4]+sred[5]+sred[6]+sred[7]) * (1.0f/CHN);
    float rstd = rsqrtf(var + 1e-5f);

    __nv_bfloat16* op = out + (size_t)row * (2*CHN);
    #pragma unroll
    for (int j = 0; j < 3; j++) {
        int cidx = tid + j*128;
        float d = (j==0) ? d0 : (j==1) ? d1 : d2;
        float val = d*rstd*g[cidx] + bt[cidx];
        __nv_bfloat16 hi = __float2bfloat16(val);
        __nv_bfloat16 lo = __float2bfloat16(val - __bfloat162float(hi));
        op[cidx] = hi;
        op[CHN + cidx] = lo;
    }
}

// ---------------- channel attention ----------------
__global__ void attn_kv_k(const float* __restrict__ qkv, float* __restrict__ attn)
{
    int bh = blockIdx.x;
    int b = bh / HEADS, h = bh % HEADS;
    const float* kb = qkv + (size_t)b * NTOK * (3*CHN) + CHN   + h*HDIM;
    const float* vb = qkv + (size_t)b * NTOK * (3*CHN) + 2*CHN + h*HDIM;

    __shared__ float ks[32][33], vs[32][33];
    int e  = threadIdx.x & 31;
    int dg = threadIdx.x >> 5;
    float acc[4] = {0.f, 0.f, 0.f, 0.f};

    for (int n0 = 0; n0 < NTOK; n0 += 32) {
        #pragma unroll
        for (int r = 0; r < 4; r++) {
            int nl = (threadIdx.x >> 5) + r*8;
            int dl = threadIdx.x & 31;
            int n = n0 + nl;
            ks[nl][dl] = (n < NTOK) ? kb[(size_t)n * (3*CHN) + dl] : 0.f;
            vs[nl][dl] = (n < NTOK) ? vb[(size_t)n * (3*CHN) + dl] : 0.f;
        }
        __syncthreads();
        #pragma unroll 8
        for (int nl = 0; nl < 32; nl++) {
            float vv = vs[nl][e];
            #pragma unroll
            for (int i = 0; i < 4; i++) acc[i] = fmaf(ks[nl][dg + 8*i], vv, acc[i]);
        }
        __syncthreads();
    }
    #pragma unroll
    for (int i = 0; i < 4; i++) {
        int d = dg + 8*i;
        attn[(size_t)bh * (HDIM*HDIM) + d*HDIM + e] = acc[i] * SCALE_K;
    }
}

__global__ void softmax32(float* __restrict__ attn)
{
    int r = blockIdx.x * 4 + (threadIdx.x >> 5);
    int lane = threadIdx.x & 31;
    float* p = attn + (size_t)r * 32;
    float v = p[lane];
    float m = v;
    #pragma unroll
    for (int o = 16; o > 0; o >>= 1) m = fmaxf(m, __shfl_xor_sync(0xffffffffu, m, o));
    float ex = expf(v - m);
    float s = ex;
    #pragma unroll
    for (int o = 16; o > 0; o >>= 1) s += __shfl_xor_sync(0xffffffffu, s, o);
    p[lane] = ex / s;
}

// out dedup split [b,n, 2C]: hi at c, lo at C+c
__global__ void attn_apply_split(const float* __restrict__ qkv, const float* __restrict__ attn,
                                 __nv_bfloat16* __restrict__ out)
{
    int bh = blockIdx.x;
    int b = bh / HEADS, h = bh % HEADS;
    int n0 = blockIdx.y * 64;

    __shared__ float As[32][33];
    __shared__ float qs[8][33];

    #pragma unroll
    for (int r = 0; r < 4; r++) {
        int idx = threadIdx.x + r*256;
        As[idx >> 5][idx & 31] = attn[(size_t)bh * (HDIM*HDIM) + idx];
    }
    const float* qb = qkv + (size_t)b * NTOK * (3*CHN) + h*HDIM;
    int d  = threadIdx.x & 31;
    int nl = threadIdx.x >> 5;
    __syncthreads();

    for (int r = 0; r < 8; r++) {
        int n = n0 + r*8 + nl;
        qs[nl][d] = (n < NTOK) ? qb[(size_t)n * (3*CHN) + d] : 0.f;
        __syncthreads();
        float acc = 0.f;
        #pragma unroll
        for (int e = 0; e < 32; e++) acc = fmaf(qs[nl][e], As[d][e], acc);
        if (n < NTOK) {
            __nv_bfloat16 hi = __float2bfloat16(acc);
            __nv_bfloat16 lo = __float2bfloat16(acc - __bfloat162float(hi));
            size_t base = ((size_t)b * NTOK + n) * (2*CHN) + h*HDIM + d;
            out[base] = hi;
            out[base + CHN] = lo;
        }
        __syncthreads();
    }
}

// ---------------- per-batch transpose (B,R,S) -> (B,S,R) ----------------
__global__ void btranspose(const float* __restrict__ in, float* __restrict__ out, int R, int S)
{
    __shared__ float tile[32][33];
    int b  = blockIdx.z;
    int r0 = blockIdx.y * 32, s0 = blockIdx.x * 32;
    const float* ip = in  + (size_t)b * R * S;
    float*       op = out + (size_t)b * R * S;

    int tx = threadIdx.x, ty = threadIdx.y;
    #pragma unroll
    for (int i = 0; i < 32; i += 8) {
        int rr = r0 + ty + i, ss = s0 + tx;
        if (rr < R && ss < S) tile[ty+i][tx] = ip[(size_t)rr * S + ss];
    }
    __syncthreads();
    #pragma unroll
    for (int i = 0; i < 32; i += 8) {
        int ss = s0 + ty + i, rr = r0 + tx;
        if (ss < S && rr < R) op[(size_t)ss * R + rr] = tile[tx][ty+i];
    }
}

// ---------------- host launcher ----------------
extern "C" void kernel_launch(void* const* d_in, const int* in_sizes, int n_in,
                              void* d_out, int out_size)
{
    const float* x      = (const float*)d_in[0];
    const float* cpe1_w = (const float*)d_in[1];
    const float* cpe1_b = (const float*)d_in[2];
    const float* n1_g   = (const float*)d_in[3];
    const float* n1_b   = (const float*)d_in[4];
    const float* qkv_w  = (const float*)d_in[5];
    const float* proj_w = (const float*)d_in[6];
    const float* proj_b = (const float*)d_in[7];
    const float* cpe2_w = (const float*)d_in[8];
    const float* cpe2_b = (const float*)d_in[9];
    const float* n2_g   = (const float*)d_in[10];
    const float* n2_b   = (const float*)d_in[11];
    const float* fc1_w  = (const float*)d_in[12];
    const float* fc1_b  = (const float*)d_in[13];
    const float* fc2_w  = (const float*)d_in[14];
    const float* fc2_b  = (const float*)d_in[15];
    float* out = (float*)d_out;

    float *p_nchwA, *p_xt, *p_qkv, *p_attn, *p_x2, *p_x3, *p_y;
    __nv_bfloat16 *p_curS, *p_aoS, *p_hidS, *p_wqkvS, *p_wprojS, *p_wfc1S, *p_wfc2S;
    cudaGetSymbolAddress((void**)&p_nchwA,  g_nchwA);
    cudaGetSymbolAddress((void**)&p_xt,     g_xt);
    cudaGetSymbolAddress((void**)&p_qkv,    g_qkv);
    cudaGetSymbolAddress((void**)&p_attn,   g_attn);
    cudaGetSymbolAddress((void**)&p_x2,     g_x2);
    cudaGetSymbolAddress((void**)&p_x3,     g_x3);
    cudaGetSymbolAddress((void**)&p_y,      g_y);
    cudaGetSymbolAddress((void**)&p_curS,   g_curS);
    cudaGetSymbolAddress((void**)&p_aoS,    g_aoS);
    cudaGetSymbolAddress((void**)&p_hidS,   g_hidS);
    cudaGetSymbolAddress((void**)&p_wqkvS,  g_wqkvS);
    cudaGetSymbolAddress((void**)&p_wprojS, g_wprojS);
    cudaGetSymbolAddress((void**)&p_wfc1S,  g_wfc1S);
    cudaGetSymbolAddress((void**)&p_wfc2S,  g_wfc2S);

    cudaFuncSetAttribute(gemm_mma, cudaFuncAttributeMaxDynamicSharedMemorySize, GEMM_SMEM);

    dim3 t328(32, 8);

    // weight splits (single launch)
    weight_split_all<<<dim3((HIDDEN*CHN + 255)/256, 4), 256>>>(
        qkv_w, p_wqkvS, proj_w, p_wprojS, fc1_w, p_wfc1S, fc2_w, p_wfc2S);

    // 1) x = x + dwconv1(x)            (NCHW)
    dwconv_res<<<BATCH*CHN, 256>>>(x, cpe1_w, cpe1_b, p_nchwA);
    // 2) transpose -> token-major xt (B,N,C)
    btranspose<<<dim3(25, 12, BATCH), t328>>>(p_nchwA, p_xt, CHN, NTOK);
    // 3) curS = split(LN(xt))
    layernorm_split<<<MROWS, 128>>>(p_xt, n1_g, n1_b, p_curS);
    // 4) qkv = cur @ qkv_w^T
    gemm_mma<<<dim3((3*CHN)/128, MROWS/128), 256, GEMM_SMEM>>>(
        p_curS, p_wqkvS, nullptr, nullptr, p_qkv, nullptr, 3*CHN, CHN, 0);
    // 5-7) channel attention
    attn_kv_k<<<BATCH*HEADS, 256>>>(p_qkv, p_attn);
    softmax32<<<(BATCH*HEADS*HDIM)/4, 128>>>(p_attn);
    attn_apply_split<<<dim3(BATCH*HEADS, 13), 256>>>(p_qkv, p_attn, p_aoS);
    // 8) x2 = xt + ao @ proj_w^T + proj_b   (token-major)
    gemm_mma<<<dim3(CHN/128, MROWS/128), 256, GEMM_SMEM>>>(
        p_aoS, p_wprojS, proj_b, p_xt, p_x2, nullptr, CHN, CHN, 0);
    // 9) x3 = x2 + dwconv2(x2)          (token-major, no transposes)
    dwconv_tok<<<dim3(HH, BATCH), CHN>>>(p_x2, cpe2_w, cpe2_b, p_x3);
    // 10) curS = split(LN(x3))
    layernorm_split<<<MROWS, 128>>>(p_x3, n2_g, n2_b, p_curS);
    // 11) hidS = split(gelu(cur @ fc1^T + b1))
    gemm_mma<<<dim3(HIDDEN/128, MROWS/128), 256, GEMM_SMEM>>>(
        p_curS, p_wfc1S, fc1_b, nullptr, nullptr, p_hidS, HIDDEN, CHN, 1);
    // 12) y = x3 + hid @ fc2^T + b2
    gemm_mma<<<dim3(CHN/128, MROWS/128), 256, GEMM_SMEM>>>(
        p_hidS, p_wfc2S, fc2_b, p_x3, p_y, nullptr, CHN, HIDDEN, 0);
    // 13) final transpose to (B,C,H,W)
    btranspose<<<dim3(12, 25, BATCH), t328>>>(p_y, out, NTOK, CHN);
}